// round 1
// baseline (speedup 1.0000x reference)
#include <cuda_runtime.h>
#include <math.h>

#define T_STEPS 16
#define BATCH   8
#define HID     64
#define HW      4096   // 64*64

// ---- scratch (static device arrays; no allocation allowed) ----
__device__ float g_out0[(size_t)BATCH * T_STEPS * HID * HW];  // layer0 hidden sequence (128 MB)
__device__ float g_c0[(size_t)BATCH * HID * HW];
__device__ float g_c1[(size_t)BATCH * HID * HW];
__device__ float g_scale[BATCH * T_STEPS * 3];

__device__ __forceinline__ float sigm_(float x) { return 1.0f / (1.0f + expf(-x)); }

// ============================================================================
// Attention: per (b,t) reduce mean+max over HxW for 3 channels, tiny MLP,
// write sigmoid scale[b][t][c].
// ============================================================================
__global__ void attn_kernel(const float* __restrict__ x,
                            const float* __restrict__ w1,
                            const float* __restrict__ w2) {
    int bt = blockIdx.x;  // 0..127 == b*16+t
    const float* base = x + (size_t)bt * 3 * HW;

    float sums[3], maxs[3];
#pragma unroll
    for (int c = 0; c < 3; c++) { sums[c] = 0.f; maxs[c] = -INFINITY; }

    for (int i = threadIdx.x; i < HW; i += 256) {
#pragma unroll
        for (int c = 0; c < 3; c++) {
            float v = base[c * HW + i];
            sums[c] += v;
            maxs[c] = fmaxf(maxs[c], v);
        }
    }
#pragma unroll
    for (int off = 16; off; off >>= 1) {
#pragma unroll
        for (int c = 0; c < 3; c++) {
            sums[c] += __shfl_xor_sync(0xffffffffu, sums[c], off);
            maxs[c] = fmaxf(maxs[c], __shfl_xor_sync(0xffffffffu, maxs[c], off));
        }
    }
    __shared__ float rs[8][3], rm[8][3];
    int wid = threadIdx.x >> 5, lid = threadIdx.x & 31;
    if (lid == 0) {
#pragma unroll
        for (int c = 0; c < 3; c++) { rs[wid][c] = sums[c]; rm[wid][c] = maxs[c]; }
    }
    __syncthreads();
    if (threadIdx.x == 0) {
        float a[3], m[3];
#pragma unroll
        for (int c = 0; c < 3; c++) { a[c] = 0.f; m[c] = -INFINITY; }
        for (int w = 0; w < 8; w++)
#pragma unroll
            for (int c = 0; c < 3; c++) { a[c] += rs[w][c]; m[c] = fmaxf(m[c], rm[w][c]); }
        float ra = 0.f, rx = 0.f;
#pragma unroll
        for (int c = 0; c < 3; c++) {
            ra += w1[c] * (a[c] * (1.0f / HW));
            rx += w1[c] * m[c];
        }
        ra = fmaxf(ra, 0.f);  // relu
        rx = fmaxf(rx, 0.f);
#pragma unroll
        for (int c = 0; c < 3; c++) {
            float s = w2[c] * ra + w2[c] * rx;
            g_scale[bt * 3 + c] = 1.0f / (1.0f + expf(-s));
        }
    }
}

// ============================================================================
// Fused ConvLSTM step: conv over [x_part ++ h_prev] producing 4 gates,
// gate nonlinearities + c/h update fused in epilogue (no 256-ch intermediate).
// Block: 256 threads; tile = 16x16 px, 16 hidden channels (=64 oc rows).
// Thread: 8 px (contiguous row) x (4 gates x 2 hc) = 64 accumulators.
// ============================================================================
struct LayerArgs {
    const float* xin;   long xin_bs;     // per-b stride (elems)
    const float* scale;                  // nullptr => 1.0; layout [b][t][3], bstride 48
    const float* hprev; long h_bs;       // nullptr at t==0
    const float* w;                      // [256][cinTot][3][3]
    const float* bias;                   // [256]
    float* cbuf;                         // [B][HID][HW], updated in place
    float* hout; long hout_bs;
    int cinX, cinTot;
};

__global__ __launch_bounds__(256, 2) void step_kernel(LayerArgs a0, LayerArgs a1, int mask) {
    int z = blockIdx.z;
    int layer;
    if (mask == 3) { layer = z >> 3; z &= 7; }
    else           { layer = mask - 1; }
    LayerArgs a = layer ? a1 : a0;
    int b = z;

    int tile = blockIdx.x;                      // 0..15 -> 4x4 tiles of 16x16
    int y0 = (tile >> 2) << 4, x0 = (tile & 3) << 4;
    int hcBase = blockIdx.y << 4;               // 0,16,32,48
    int tid = threadIdx.x;
    int og = tid >> 5, pg = tid & 31;
    int r = pg >> 1, chf = pg & 1;
    int py = y0 + r, pxb = x0 + chf * 8;

    __shared__ float sIn[18 * 19];   // stride 19 -> conflict-free for this pattern
    __shared__ float sW[64 * 9];

    float acc[4][2][8];
#pragma unroll
    for (int g = 0; g < 4; g++)
#pragma unroll
        for (int j = 0; j < 2; j++) {
            float bv = a.bias[(g << 6) + hcBase + og * 2 + j];
#pragma unroll
            for (int p = 0; p < 8; p++) acc[g][j][p] = bv;
        }

    int nCin = a.hprev ? a.cinTot : a.cinX;
    for (int cin = 0; cin < nCin; cin++) {
        __syncthreads();
        const float* src;
        float mul = 1.0f;
        if (cin < a.cinX) {
            src = a.xin + (size_t)b * a.xin_bs + (size_t)cin * HW;
            if (a.scale) mul = a.scale[b * 48 + cin];
        } else {
            src = a.hprev + (size_t)b * a.h_bs + (size_t)(cin - a.cinX) * HW;
        }
        // input halo tile 18x18
#pragma unroll
        for (int it = 0; it < 2; it++) {
            int i = tid + it * 256;
            if (i < 324) {
                int iy = i / 18, ix = i - iy * 18;
                int gy = y0 + iy - 1, gx = x0 + ix - 1;
                float v = 0.f;
                if ((unsigned)gy < 64u && (unsigned)gx < 64u) v = src[gy * 64 + gx] * mul;
                sIn[iy * 19 + ix] = v;
            }
        }
        // weights: 64 local oc x 9
        const float* wcin = a.w + (size_t)cin * 9;
        long ocStride = (long)a.cinTot * 9;
#pragma unroll
        for (int it = 0; it < 3; it++) {
            int i = tid + it * 256;
            if (i < 576) {
                int ocl = i / 9, k = i - ocl * 9;
                int g = ocl >> 4, hcl = ocl & 15;
                int oc = (g << 6) + hcBase + hcl;
                sW[i] = wcin[(size_t)oc * ocStride + k];
            }
        }
        __syncthreads();

        const float* rowBase = &sIn[r * 19 + chf * 8];
#pragma unroll
        for (int dy = 0; dy < 3; dy++) {
            float inv[10];
#pragma unroll
            for (int i2 = 0; i2 < 10; i2++) inv[i2] = rowBase[dy * 19 + i2];
#pragma unroll
            for (int g = 0; g < 4; g++)
#pragma unroll
                for (int j = 0; j < 2; j++) {
                    int w9 = ((g << 4) + og * 2 + j) * 9 + dy * 3;
                    float wa = sW[w9], wb = sW[w9 + 1], wc = sW[w9 + 2];
#pragma unroll
                    for (int p = 0; p < 8; p++) {
                        float t = acc[g][j][p];
                        t = fmaf(wa, inv[p], t);
                        t = fmaf(wb, inv[p + 1], t);
                        t = fmaf(wc, inv[p + 2], t);
                        acc[g][j][p] = t;
                    }
                }
        }
    }

    // fused LSTM epilogue: gates order (i, f, o, g)
    bool first = (a.hprev == nullptr);
#pragma unroll
    for (int j = 0; j < 2; j++) {
        int hc = hcBase + og * 2 + j;
        size_t cidx = ((size_t)b * HID + hc) * HW + py * 64 + pxb;
        size_t hidx = (size_t)b * a.hout_bs + (size_t)hc * HW + py * 64 + pxb;
#pragma unroll
        for (int p = 0; p < 8; p++) {
            float ig = sigm_(acc[0][j][p]);
            float fg = sigm_(acc[1][j][p]);
            float oo = sigm_(acc[2][j][p]);
            float gg = tanhf(acc[3][j][p]);
            float cp = first ? 0.f : a.cbuf[cidx + p];
            float cn = fg * cp + ig * gg;
            a.cbuf[cidx + p] = cn;
            a.hout[hidx + p] = oo * tanhf(cn);
        }
    }
}

// ============================================================================
// finalize: h1 = out1[:, T-1], c1 = g_c1
// ============================================================================
__global__ void finalize_kernel(float* __restrict__ dout) {
    const size_t NPB = (size_t)HID * HW;           // 262144
    const size_t N = (size_t)BATCH * NPB;          // 2097152
    size_t i = (size_t)blockIdx.x * 256 + threadIdx.x;
    if (i < N) {
        size_t b = i / NPB, rest = i - b * NPB;
        dout[33554432 + i] = dout[((size_t)b * T_STEPS + 15) * NPB + rest];
        dout[35651584 + i] = g_c1[i];
    }
}

// ============================================================================
extern "C" void kernel_launch(void* const* d_in, const int* in_sizes, int n_in,
                              void* d_out, int out_size) {
    const float* x   = (const float*)d_in[0];
    const float* w1a = (const float*)d_in[1];
    const float* w2a = (const float*)d_in[2];
    const float* cw0 = (const float*)d_in[3];
    const float* cb0 = (const float*)d_in[4];
    const float* cw1 = (const float*)d_in[5];
    const float* cb1 = (const float*)d_in[6];
    float* out = (float*)d_out;

    float *out0, *c0, *c1, *scale;
    cudaGetSymbolAddress((void**)&out0, g_out0);
    cudaGetSymbolAddress((void**)&c0, g_c0);
    cudaGetSymbolAddress((void**)&c1, g_c1);
    cudaGetSymbolAddress((void**)&scale, g_scale);

    attn_kernel<<<128, 256>>>(x, w1a, w2a);

    // pipelined: launch s runs layer0 @ t=s and layer1 @ t=s-1 (independent)
    for (int s = 0; s <= T_STEPS; s++) {
        LayerArgs a0 = {}, a1 = {};
        int mask = 0;
        if (s < T_STEPS) {
            mask |= 1;
            a0.xin = x + (size_t)s * 3 * HW;  a0.xin_bs = (long)T_STEPS * 3 * HW;
            a0.scale = scale + s * 3;
            a0.hprev = (s > 0) ? out0 + (size_t)(s - 1) * HID * HW : nullptr;
            a0.h_bs = (long)T_STEPS * HID * HW;
            a0.w = cw0; a0.bias = cb0;
            a0.cbuf = c0;
            a0.hout = out0 + (size_t)s * HID * HW;  a0.hout_bs = (long)T_STEPS * HID * HW;
            a0.cinX = 3; a0.cinTot = 3 + HID;
        }
        if (s >= 1) {
            int t = s - 1;
            mask |= 2;
            a1.xin = out0 + (size_t)t * HID * HW;  a1.xin_bs = (long)T_STEPS * HID * HW;
            a1.scale = nullptr;
            a1.hprev = (t > 0) ? out + (size_t)(t - 1) * HID * HW : nullptr;
            a1.h_bs = (long)T_STEPS * HID * HW;
            a1.w = cw1; a1.bias = cb1;
            a1.cbuf = c1;
            a1.hout = out + (size_t)t * HID * HW;  a1.hout_bs = (long)T_STEPS * HID * HW;
            a1.cinX = HID; a1.cinTot = 2 * HID;
        }
        dim3 grid(16, 4, (mask == 3) ? 16 : 8);
        step_kernel<<<grid, 256>>>(a0, a1, mask);
    }

    finalize_kernel<<<(BATCH * HID * HW + 255) / 256, 256>>>(out);
}

// round 2
// speedup vs baseline: 1.1309x; 1.1309x over previous
#include <cuda_runtime.h>
#include <math.h>

#define T_STEPS 16
#define BATCH   8
#define HID     64
#define HW      4096   // 64*64

typedef unsigned long long ull;

// ---- scratch (static device arrays; no allocation allowed) ----
__device__ float g_out0[(size_t)BATCH * T_STEPS * HID * HW];  // layer0 hidden sequence
__device__ float g_c0[(size_t)BATCH * HID * HW];
__device__ float g_c1[(size_t)BATCH * HID * HW];
__device__ float g_scale[BATCH * T_STEPS * 3];

__device__ __forceinline__ float sigf(float x) { return 1.0f / (1.0f + __expf(-x)); }
__device__ __forceinline__ float tanhfast(float x) { return 2.0f / (1.0f + __expf(-2.0f * x)) - 1.0f; }

__device__ __forceinline__ ull pack2(float lo, float hi) {
    ull r; asm("mov.b64 %0, {%1, %2};" : "=l"(r) : "f"(lo), "f"(hi)); return r;
}
__device__ __forceinline__ void unpack2(ull v, float& lo, float& hi) {
    asm("mov.b64 {%0, %1}, %2;" : "=f"(lo), "=f"(hi) : "l"(v));
}
#define FMA2(d, a, b, c) asm("fma.rn.f32x2 %0, %1, %2, %3;" : "=l"(d) : "l"(a), "l"(b), "l"(c))

// ============================================================================
// Attention: per (b,t) reduce mean+max over HxW for 3 channels, tiny MLP.
// ============================================================================
__global__ void attn_kernel(const float* __restrict__ x,
                            const float* __restrict__ w1,
                            const float* __restrict__ w2) {
    int bt = blockIdx.x;
    const float* base = x + (size_t)bt * 3 * HW;

    float sums[3], maxs[3];
#pragma unroll
    for (int c = 0; c < 3; c++) { sums[c] = 0.f; maxs[c] = -INFINITY; }
    for (int i = threadIdx.x; i < HW; i += 256) {
#pragma unroll
        for (int c = 0; c < 3; c++) {
            float v = base[c * HW + i];
            sums[c] += v;
            maxs[c] = fmaxf(maxs[c], v);
        }
    }
#pragma unroll
    for (int off = 16; off; off >>= 1) {
#pragma unroll
        for (int c = 0; c < 3; c++) {
            sums[c] += __shfl_xor_sync(0xffffffffu, sums[c], off);
            maxs[c] = fmaxf(maxs[c], __shfl_xor_sync(0xffffffffu, maxs[c], off));
        }
    }
    __shared__ float rs[8][3], rm[8][3];
    int wid = threadIdx.x >> 5, lid = threadIdx.x & 31;
    if (lid == 0) {
#pragma unroll
        for (int c = 0; c < 3; c++) { rs[wid][c] = sums[c]; rm[wid][c] = maxs[c]; }
    }
    __syncthreads();
    if (threadIdx.x == 0) {
        float a[3], m[3];
#pragma unroll
        for (int c = 0; c < 3; c++) { a[c] = 0.f; m[c] = -INFINITY; }
        for (int w = 0; w < 8; w++)
#pragma unroll
            for (int c = 0; c < 3; c++) { a[c] += rs[w][c]; m[c] = fmaxf(m[c], rm[w][c]); }
        float ra = 0.f, rx = 0.f;
#pragma unroll
        for (int c = 0; c < 3; c++) {
            ra += w1[c] * (a[c] * (1.0f / HW));
            rx += w1[c] * m[c];
        }
        ra = fmaxf(ra, 0.f);
        rx = fmaxf(rx, 0.f);
#pragma unroll
        for (int c = 0; c < 3; c++) {
            float s = w2[c] * ra + w2[c] * rx;
            g_scale[bt * 3 + c] = 1.0f / (1.0f + expf(-s));
        }
    }
}

// ============================================================================
// Fused ConvLSTM step, f32x2-packed direct conv.
// Block: 256 thr = 16 rows x 16 hidden-channels; tile 16x16 px, 16 hc.
// Thread: 16 px (one row) x 4 gates = 64 acc floats = 32 f32x2 regs.
// SMEM: halo tile stored twice (A normal, B shifted by 1 col) so every tap
// reads an aligned LDS.64 pair; weights stored pre-duplicated (w,w).
// Double-buffered; one __syncthreads per cin.
// ============================================================================
struct LayerArgs {
    const float* xin;   long xin_bs;
    const float* scale;                  // nullptr => 1.0; [b][t][3], bstride 48
    const float* hprev; long h_bs;       // nullptr at t==0
    const float* w;                      // [256][cinTot][3][3]
    const float* bias;                   // [256]
    float* cbuf;
    float* hout; long hout_bs;
    int cinX, cinTot;
};

__global__ __launch_bounds__(256, 2) void step_kernel(LayerArgs a0, LayerArgs a1, int mask) {
    int z = blockIdx.z;
    int layer;
    if (mask == 3) { layer = z >> 3; z &= 7; }
    else           { layer = mask - 1; }
    LayerArgs a = layer ? a1 : a0;
    int b = z;

    int tile = blockIdx.x;
    int y0 = (tile >> 2) << 4, x0 = (tile & 3) << 4;
    int hcBase = blockIdx.y << 4;
    int tid = threadIdx.x;
    int r = tid >> 4, hcl = tid & 15;

    __shared__ __align__(16) float sA[2][18 * 20];
    __shared__ __align__(16) float sB[2][18 * 20];
    __shared__ __align__(16) float sW[2][64 * 9 * 2];

    // ---- precompute fill indices ----
    // input: slot0 = tid (<324 always), slot1 = tid+256 (valid if tid<68)
    int iy0 = tid / 18, ix0 = tid - iy0 * 18;
    int j1 = tid + 256;
    int iy1 = j1 / 18, ix1 = j1 - iy1 * 18;
    bool v1 = (j1 < 324);
    int gy0 = y0 + iy0 - 1, gx0 = x0 + ix0 - 1;
    int gy1 = y0 + iy1 - 1, gx1 = x0 + ix1 - 1;
    bool in0 = ((unsigned)gy0 < 64u) && ((unsigned)gx0 < 64u);
    bool in1 = v1 && ((unsigned)gy1 < 64u) && ((unsigned)gx1 < 64u);

    // weights: slots tid, tid+256, tid+512 (<576; third valid if tid<64)
    long ocStride = (long)a.cinTot * 9;
    long goff[3]; int swoff[3]; bool wv[3];
#pragma unroll
    for (int it = 0; it < 3; it++) {
        int i = tid + it * 256;
        wv[it] = (i < 576);
        int ii = wv[it] ? i : 0;
        int ocl = ii / 9, k = ii - ocl * 9;
        int oc = ((ocl >> 4) << 6) + hcBase + (ocl & 15);
        goff[it] = (long)oc * ocStride + k;
        swoff[it] = ii * 2;
    }

    // ---- accumulators (bias-initialized) ----
    ull acc2[4][8];
#pragma unroll
    for (int g = 0; g < 4; g++) {
        float bv = a.bias[(g << 6) + hcBase + hcl];
        ull bp = pack2(bv, bv);
#pragma unroll
        for (int k = 0; k < 8; k++) acc2[g][k] = bp;
    }

    int nCin = a.hprev ? a.cinTot : a.cinX;

    // ---- fill helper ----
    auto fill = [&](int c, int s) {
        const float* src;
        float mul = 1.0f;
        if (c < a.cinX) {
            src = a.xin + (size_t)b * a.xin_bs + (size_t)c * HW;
            if (a.scale) mul = a.scale[b * 48 + c];
        } else {
            src = a.hprev + (size_t)b * a.h_bs + (size_t)(c - a.cinX) * HW;
        }
        {
            float v = in0 ? src[gy0 * 64 + gx0] * mul : 0.f;
            sA[s][iy0 * 20 + ix0] = v;
            if (ix0 >= 1) sB[s][iy0 * 20 + ix0 - 1] = v;
        }
        if (v1) {
            float v = in1 ? src[gy1 * 64 + gx1] * mul : 0.f;
            sA[s][iy1 * 20 + ix1] = v;
            if (ix1 >= 1) sB[s][iy1 * 20 + ix1 - 1] = v;
        }
        const float* wsrc = a.w + (size_t)c * 9;
#pragma unroll
        for (int it = 0; it < 3; it++) {
            if (wv[it]) {
                float wval = wsrc[goff[it]];
                *reinterpret_cast<ull*>(&sW[s][swoff[it]]) = pack2(wval, wval);
            }
        }
    };

    fill(0, 0);
    __syncthreads();

    for (int c = 0; c < nCin; c++) {
        int s = c & 1;
        if (c + 1 < nCin) fill(c + 1, s ^ 1);

#pragma unroll
        for (int dy = 0; dy < 3; dy++) {
            const ull* Ap = reinterpret_cast<const ull*>(&sA[s][(r + dy) * 20]);
            const ull* Bp = reinterpret_cast<const ull*>(&sB[s][(r + dy) * 20]);
            ull Av[9], Bv[8];
#pragma unroll
            for (int k = 0; k < 9; k++) Av[k] = Ap[k];
#pragma unroll
            for (int k = 0; k < 8; k++) Bv[k] = Bp[k];
#pragma unroll
            for (int g = 0; g < 4; g++) {
                const ull* Wp = reinterpret_cast<const ull*>(
                    &sW[s][(((g << 4) + hcl) * 9 + dy * 3) * 2]);
                ull wa = Wp[0], wb = Wp[1], wc = Wp[2];
#pragma unroll
                for (int k = 0; k < 8; k++) {
                    FMA2(acc2[g][k], wa, Av[k], acc2[g][k]);
                    FMA2(acc2[g][k], wb, Bv[k], acc2[g][k]);
                    FMA2(acc2[g][k], wc, Av[k + 1], acc2[g][k]);
                }
            }
        }
        __syncthreads();
    }

    // ---- fused LSTM epilogue: gates (i, f, o, g) ----
    bool first = (a.hprev == nullptr);
    int hc = hcBase + hcl;
    int py = y0 + r;
    size_t cbase = ((size_t)b * HID + hc) * HW + py * 64 + x0;
    size_t hbase = (size_t)b * a.hout_bs + (size_t)hc * HW + py * 64 + x0;
#pragma unroll
    for (int k = 0; k < 8; k++) {
        float i0, i1, f0, f1, o0, o1, q0, q1;
        unpack2(acc2[0][k], i0, i1);
        unpack2(acc2[1][k], f0, f1);
        unpack2(acc2[2][k], o0, o1);
        unpack2(acc2[3][k], q0, q1);
        float2 cp = first ? make_float2(0.f, 0.f)
                          : *reinterpret_cast<const float2*>(&a.cbuf[cbase + 2 * k]);
        float cn0 = sigf(f0) * cp.x + sigf(i0) * tanhfast(q0);
        float cn1 = sigf(f1) * cp.y + sigf(i1) * tanhfast(q1);
        float hn0 = sigf(o0) * tanhfast(cn0);
        float hn1 = sigf(o1) * tanhfast(cn1);
        *reinterpret_cast<float2*>(&a.cbuf[cbase + 2 * k]) = make_float2(cn0, cn1);
        *reinterpret_cast<float2*>(&a.hout[hbase + 2 * k]) = make_float2(hn0, hn1);
    }
}

// ============================================================================
__global__ void finalize_kernel(float* __restrict__ dout) {
    const size_t NPB = (size_t)HID * HW;
    const size_t N = (size_t)BATCH * NPB;
    size_t i = (size_t)blockIdx.x * 256 + threadIdx.x;
    if (i < N) {
        size_t b = i / NPB, rest = i - b * NPB;
        dout[33554432 + i] = dout[((size_t)b * T_STEPS + 15) * NPB + rest];
        dout[35651584 + i] = g_c1[i];
    }
}

// ============================================================================
extern "C" void kernel_launch(void* const* d_in, const int* in_sizes, int n_in,
                              void* d_out, int out_size) {
    const float* x   = (const float*)d_in[0];
    const float* w1a = (const float*)d_in[1];
    const float* w2a = (const float*)d_in[2];
    const float* cw0 = (const float*)d_in[3];
    const float* cb0 = (const float*)d_in[4];
    const float* cw1 = (const float*)d_in[5];
    const float* cb1 = (const float*)d_in[6];
    float* out = (float*)d_out;

    float *out0, *c0, *c1, *scale;
    cudaGetSymbolAddress((void**)&out0, g_out0);
    cudaGetSymbolAddress((void**)&c0, g_c0);
    cudaGetSymbolAddress((void**)&c1, g_c1);
    cudaGetSymbolAddress((void**)&scale, g_scale);

    attn_kernel<<<128, 256>>>(x, w1a, w2a);

    for (int s = 0; s <= T_STEPS; s++) {
        LayerArgs a0 = {}, a1 = {};
        int mask = 0;
        if (s < T_STEPS) {
            mask |= 1;
            a0.xin = x + (size_t)s * 3 * HW;  a0.xin_bs = (long)T_STEPS * 3 * HW;
            a0.scale = scale + s * 3;
            a0.hprev = (s > 0) ? out0 + (size_t)(s - 1) * HID * HW : nullptr;
            a0.h_bs = (long)T_STEPS * HID * HW;
            a0.w = cw0; a0.bias = cb0;
            a0.cbuf = c0;
            a0.hout = out0 + (size_t)s * HID * HW;  a0.hout_bs = (long)T_STEPS * HID * HW;
            a0.cinX = 3; a0.cinTot = 3 + HID;
        }
        if (s >= 1) {
            int t = s - 1;
            mask |= 2;
            a1.xin = out0 + (size_t)t * HID * HW;  a1.xin_bs = (long)T_STEPS * HID * HW;
            a1.scale = nullptr;
            a1.hprev = (t > 0) ? out + (size_t)(t - 1) * HID * HW : nullptr;
            a1.h_bs = (long)T_STEPS * HID * HW;
            a1.w = cw1; a1.bias = cb1;
            a1.cbuf = c1;
            a1.hout = out + (size_t)t * HID * HW;  a1.hout_bs = (long)T_STEPS * HID * HW;
            a1.cinX = HID; a1.cinTot = 2 * HID;
        }
        dim3 grid(16, 4, (mask == 3) ? 16 : 8);
        step_kernel<<<grid, 256>>>(a0, a1, mask);
    }

    finalize_kernel<<<(BATCH * HID * HW + 255) / 256, 256>>>(out);
}

// round 3
// speedup vs baseline: 1.1434x; 1.0111x over previous
#include <cuda_runtime.h>
#include <math.h>

#define T_STEPS 16
#define BATCH   8
#define HID     64
#define HW      4096   // 64*64

typedef unsigned long long ull;

// ---- scratch (static device arrays; no allocation allowed) ----
__device__ float g_out0[(size_t)BATCH * T_STEPS * HID * HW];  // layer0 hidden sequence
__device__ float g_c0[(size_t)BATCH * HID * HW];
__device__ float g_c1[(size_t)BATCH * HID * HW];
__device__ float g_scale[BATCH * T_STEPS * 3];

__device__ __forceinline__ float sigf(float x) { return 1.0f / (1.0f + __expf(-x)); }
__device__ __forceinline__ float tanhfast(float x) { return 2.0f / (1.0f + __expf(-2.0f * x)) - 1.0f; }

__device__ __forceinline__ ull pack2(float lo, float hi) {
    ull r; asm("mov.b64 %0, {%1, %2};" : "=l"(r) : "f"(lo), "f"(hi)); return r;
}
__device__ __forceinline__ void unpack2(ull v, float& lo, float& hi) {
    asm("mov.b64 {%0, %1}, %2;" : "=f"(lo), "=f"(hi) : "l"(v));
}
#define FMA2(d, a, b, c) asm("fma.rn.f32x2 %0, %1, %2, %3;" : "=l"(d) : "l"(a), "l"(b), "l"(c))

// ============================================================================
// Attention
// ============================================================================
__global__ void attn_kernel(const float* __restrict__ x,
                            const float* __restrict__ w1,
                            const float* __restrict__ w2) {
    int bt = blockIdx.x;
    const float* base = x + (size_t)bt * 3 * HW;

    float sums[3], maxs[3];
#pragma unroll
    for (int c = 0; c < 3; c++) { sums[c] = 0.f; maxs[c] = -INFINITY; }
    for (int i = threadIdx.x; i < HW; i += 256) {
#pragma unroll
        for (int c = 0; c < 3; c++) {
            float v = base[c * HW + i];
            sums[c] += v;
            maxs[c] = fmaxf(maxs[c], v);
        }
    }
#pragma unroll
    for (int off = 16; off; off >>= 1) {
#pragma unroll
        for (int c = 0; c < 3; c++) {
            sums[c] += __shfl_xor_sync(0xffffffffu, sums[c], off);
            maxs[c] = fmaxf(maxs[c], __shfl_xor_sync(0xffffffffu, maxs[c], off));
        }
    }
    __shared__ float rs[8][3], rm[8][3];
    int wid = threadIdx.x >> 5, lid = threadIdx.x & 31;
    if (lid == 0) {
#pragma unroll
        for (int c = 0; c < 3; c++) { rs[wid][c] = sums[c]; rm[wid][c] = maxs[c]; }
    }
    __syncthreads();
    if (threadIdx.x == 0) {
        float a[3], m[3];
#pragma unroll
        for (int c = 0; c < 3; c++) { a[c] = 0.f; m[c] = -INFINITY; }
        for (int w = 0; w < 8; w++)
#pragma unroll
            for (int c = 0; c < 3; c++) { a[c] += rs[w][c]; m[c] = fmaxf(m[c], rm[w][c]); }
        float ra = 0.f, rx = 0.f;
#pragma unroll
        for (int c = 0; c < 3; c++) {
            ra += w1[c] * (a[c] * (1.0f / HW));
            rx += w1[c] * m[c];
        }
        ra = fmaxf(ra, 0.f);
        rx = fmaxf(rx, 0.f);
#pragma unroll
        for (int c = 0; c < 3; c++) {
            float s = w2[c] * ra + w2[c] * rx;
            g_scale[bt * 3 + c] = 1.0f / (1.0f + expf(-s));
        }
    }
}

// ============================================================================
// Fused ConvLSTM step: f32x2 direct conv, TWO cins per double-buffered stage
// (one __syncthreads per 2 cins), long-CTAs-first z ordering.
// ============================================================================
struct LayerArgs {
    const float* xin;   long xin_bs;
    const float* scale;                  // nullptr => 1.0; [b][t][3], bstride 48
    const float* hprev; long h_bs;       // nullptr at t==0
    const float* w;                      // [256][cinTot][3][3]
    const float* bias;                   // [256]
    float* cbuf;
    float* hout; long hout_bs;
    int cinX, cinTot;
};

__global__ __launch_bounds__(256, 2) void step_kernel(LayerArgs a0, LayerArgs a1, int mask) {
    int z = blockIdx.z;
    int layer;
    if (mask == 3) { layer = (z < 8) ? 1 : 0; z &= 7; }  // layer1 (long) first
    else           { layer = mask - 1; }
    LayerArgs a = layer ? a1 : a0;
    int b = z;

    int tile = blockIdx.x;
    int y0 = (tile >> 2) << 4, x0 = (tile & 3) << 4;
    int hcBase = blockIdx.y << 4;
    int tid = threadIdx.x;
    int r = tid >> 4, hcl = tid & 15;

    // [stage][cin-in-pair][...]
    __shared__ __align__(16) float sA[2][2][18 * 20];
    __shared__ __align__(16) float sB[2][2][18 * 20];
    __shared__ __align__(16) float sW[2][2][64 * 9 * 2];

    // ---- precompute fill indices ----
    int iy0 = tid / 18, ix0 = tid - iy0 * 18;
    int j1 = tid + 256;
    int iy1 = j1 / 18, ix1 = j1 - iy1 * 18;
    bool v1 = (j1 < 324);
    int gy0 = y0 + iy0 - 1, gx0 = x0 + ix0 - 1;
    int gy1 = y0 + iy1 - 1, gx1 = x0 + ix1 - 1;
    bool in0 = ((unsigned)gy0 < 64u) && ((unsigned)gx0 < 64u);
    bool in1 = v1 && ((unsigned)gy1 < 64u) && ((unsigned)gx1 < 64u);
    int gofs0 = gy0 * 64 + gx0, gofs1 = gy1 * 64 + gx1;
    int sofsA0 = iy0 * 20 + ix0, sofsA1 = iy1 * 20 + ix1;

    long ocStride = (long)a.cinTot * 9;
    long goff[3]; int swoff[3]; bool wv[3];
#pragma unroll
    for (int it = 0; it < 3; it++) {
        int i = tid + it * 256;
        wv[it] = (i < 576);
        int ii = wv[it] ? i : 0;
        int ocl = ii / 9, k = ii - ocl * 9;
        int oc = ((ocl >> 4) << 6) + hcBase + (ocl & 15);
        goff[it] = (long)oc * ocStride + k;
        swoff[it] = ii * 2;
    }

    // ---- accumulators (bias-initialized) ----
    ull acc2[4][8];
#pragma unroll
    for (int g = 0; g < 4; g++) {
        float bv = a.bias[(g << 6) + hcBase + hcl];
        ull bp = pack2(bv, bv);
#pragma unroll
        for (int k = 0; k < 8; k++) acc2[g][k] = bp;
    }

    int nCin = a.hprev ? a.cinTot : a.cinX;
    int nStage = (nCin + 1) >> 1;

    // ---- fill one cin into (stage s, slot cc) ----
    auto fill1 = [&](int c, int s, int cc) {
        const float* src;
        float mul = 1.0f;
        if (c < a.cinX) {
            src = a.xin + (size_t)b * a.xin_bs + (size_t)c * HW;
            if (a.scale) mul = a.scale[b * 48 + c];
        } else {
            src = a.hprev + (size_t)b * a.h_bs + (size_t)(c - a.cinX) * HW;
        }
        {
            float v = in0 ? src[gofs0] * mul : 0.f;
            sA[s][cc][sofsA0] = v;
            if (ix0 >= 1) sB[s][cc][sofsA0 - 1] = v;
        }
        if (v1) {
            float v = in1 ? src[gofs1] * mul : 0.f;
            sA[s][cc][sofsA1] = v;
            if (ix1 >= 1) sB[s][cc][sofsA1 - 1] = v;
        }
        const float* wsrc = a.w + (size_t)c * 9;
#pragma unroll
        for (int it = 0; it < 3; it++) {
            if (wv[it]) {
                float wval = wsrc[goff[it]];
                *reinterpret_cast<ull*>(&sW[s][cc][swoff[it]]) = pack2(wval, wval);
            }
        }
    };
    auto fillpair = [&](int st, int s) {
        int c0 = 2 * st;
        fill1(c0, s, 0);
        if (c0 + 1 < nCin) fill1(c0 + 1, s, 1);
    };

    fillpair(0, 0);
    __syncthreads();

    for (int st = 0; st < nStage; st++) {
        int s = st & 1;
        if (st + 1 < nStage) fillpair(st + 1, s ^ 1);

#pragma unroll
        for (int cc = 0; cc < 2; cc++) {
            if (2 * st + cc >= nCin) break;
            const float* __restrict__ pA = sA[s][cc];
            const float* __restrict__ pB = sB[s][cc];
            const float* __restrict__ pW = sW[s][cc];
#pragma unroll
            for (int dy = 0; dy < 3; dy++) {
                const ull* Ap = reinterpret_cast<const ull*>(&pA[(r + dy) * 20]);
                const ull* Bp = reinterpret_cast<const ull*>(&pB[(r + dy) * 20]);
                ull Av[9], Bv[8];
#pragma unroll
                for (int k = 0; k < 9; k++) Av[k] = Ap[k];
#pragma unroll
                for (int k = 0; k < 8; k++) Bv[k] = Bp[k];
#pragma unroll
                for (int g = 0; g < 4; g++) {
                    const ull* Wp = reinterpret_cast<const ull*>(
                        &pW[(((g << 4) + hcl) * 9 + dy * 3) * 2]);
                    ull wa = Wp[0], wb = Wp[1], wc = Wp[2];
#pragma unroll
                    for (int k = 0; k < 8; k++) {
                        FMA2(acc2[g][k], wa, Av[k], acc2[g][k]);
                        FMA2(acc2[g][k], wb, Bv[k], acc2[g][k]);
                        FMA2(acc2[g][k], wc, Av[k + 1], acc2[g][k]);
                    }
                }
            }
        }
        __syncthreads();
    }

    // ---- fused LSTM epilogue: gates (i, f, o, g) ----
    bool first = (a.hprev == nullptr);
    int hc = hcBase + hcl;
    int py = y0 + r;
    size_t cbase = ((size_t)b * HID + hc) * HW + py * 64 + x0;
    size_t hbase = (size_t)b * a.hout_bs + (size_t)hc * HW + py * 64 + x0;
#pragma unroll
    for (int k = 0; k < 8; k++) {
        float i0, i1, f0, f1, o0, o1, q0, q1;
        unpack2(acc2[0][k], i0, i1);
        unpack2(acc2[1][k], f0, f1);
        unpack2(acc2[2][k], o0, o1);
        unpack2(acc2[3][k], q0, q1);
        float2 cp = first ? make_float2(0.f, 0.f)
                          : *reinterpret_cast<const float2*>(&a.cbuf[cbase + 2 * k]);
        float cn0 = sigf(f0) * cp.x + sigf(i0) * tanhfast(q0);
        float cn1 = sigf(f1) * cp.y + sigf(i1) * tanhfast(q1);
        float hn0 = sigf(o0) * tanhfast(cn0);
        float hn1 = sigf(o1) * tanhfast(cn1);
        *reinterpret_cast<float2*>(&a.cbuf[cbase + 2 * k]) = make_float2(cn0, cn1);
        *reinterpret_cast<float2*>(&a.hout[hbase + 2 * k]) = make_float2(hn0, hn1);
    }
}

// ============================================================================
__global__ void finalize_kernel(float* __restrict__ dout) {
    const size_t NPB = (size_t)HID * HW;
    const size_t N = (size_t)BATCH * NPB;
    size_t i = (size_t)blockIdx.x * 256 + threadIdx.x;
    if (i < N) {
        size_t b = i / NPB, rest = i - b * NPB;
        dout[33554432 + i] = dout[((size_t)b * T_STEPS + 15) * NPB + rest];
        dout[35651584 + i] = g_c1[i];
    }
}

// ============================================================================
extern "C" void kernel_launch(void* const* d_in, const int* in_sizes, int n_in,
                              void* d_out, int out_size) {
    const float* x   = (const float*)d_in[0];
    const float* w1a = (const float*)d_in[1];
    const float* w2a = (const float*)d_in[2];
    const float* cw0 = (const float*)d_in[3];
    const float* cb0 = (const float*)d_in[4];
    const float* cw1 = (const float*)d_in[5];
    const float* cb1 = (const float*)d_in[6];
    float* out = (float*)d_out;

    float *out0, *c0, *c1, *scale;
    cudaGetSymbolAddress((void**)&out0, g_out0);
    cudaGetSymbolAddress((void**)&c0, g_c0);
    cudaGetSymbolAddress((void**)&c1, g_c1);
    cudaGetSymbolAddress((void**)&scale, g_scale);

    attn_kernel<<<128, 256>>>(x, w1a, w2a);

    for (int s = 0; s <= T_STEPS; s++) {
        LayerArgs a0 = {}, a1 = {};
        int mask = 0;
        if (s < T_STEPS) {
            mask |= 1;
            a0.xin = x + (size_t)s * 3 * HW;  a0.xin_bs = (long)T_STEPS * 3 * HW;
            a0.scale = scale + s * 3;
            a0.hprev = (s > 0) ? out0 + (size_t)(s - 1) * HID * HW : nullptr;
            a0.h_bs = (long)T_STEPS * HID * HW;
            a0.w = cw0; a0.bias = cb0;
            a0.cbuf = c0;
            a0.hout = out0 + (size_t)s * HID * HW;  a0.hout_bs = (long)T_STEPS * HID * HW;
            a0.cinX = 3; a0.cinTot = 3 + HID;
        }
        if (s >= 1) {
            int t = s - 1;
            mask |= 2;
            a1.xin = out0 + (size_t)t * HID * HW;  a1.xin_bs = (long)T_STEPS * HID * HW;
            a1.scale = nullptr;
            a1.hprev = (t > 0) ? out + (size_t)(t - 1) * HID * HW : nullptr;
            a1.h_bs = (long)T_STEPS * HID * HW;
            a1.w = cw1; a1.bias = cb1;
            a1.cbuf = c1;
            a1.hout = out + (size_t)t * HID * HW;  a1.hout_bs = (long)T_STEPS * HID * HW;
            a1.cinX = HID; a1.cinTot = 2 * HID;
        }
        dim3 grid(16, 4, (mask == 3) ? 16 : 8);
        step_kernel<<<grid, 256>>>(a0, a1, mask);
    }

    finalize_kernel<<<(BATCH * HID * HW + 255) / 256, 256>>>(out);
}